// round 1
// baseline (speedup 1.0000x reference)
#include <cuda_runtime.h>
#include <stdint.h>

// VTM "downsampler" (as specified by the reference, which effectively samples
// input at i/4 with 4 sub-phases). Separable 6-tap filter, 4 phases.
//
// Input : x  (8,3,1080,1920) float32 (integer-valued 0..255)
// Output: out(8,3, 540, 960) float32
//
// Exact integer arithmetic (all sums < 2^24), bit-exact vs reference.

#define IH 1080
#define IW 1920
#define OH 540
#define OW 960
#define NIMG 24            // B*C = 8*3

#define TJ 20              // output rows per block (must be multiple of 4)
#define NR 10              // staged input rows  = TJ/4 + 5
#define XC 245             // staged input cols  = OW/4 + 5  (holds global cols -2..242, clamped)
#define NBAND (OH / TJ)    // 27

// Phase-p (p = idx & 3) filter taps for k = 3..8 (FILTER rows 0,4,8,12)
__device__ const int CFILT[24] = {
    0,   0, 128,   0,   0, 0,
    5, -18, 114,  36, -10, 1,
    4, -19,  79,  79, -19, 4,
    1, -10,  36, 114, -18, 5
};

__global__ __launch_bounds__(256)
void vtm_down_kernel(const float* __restrict__ x, float* __restrict__ out) {
    const int bc   = blockIdx.y;            // image index 0..23
    const int band = blockIdx.x;            // 0..26
    const int j0   = band * TJ;             // first output row of this band
    const int rbase = (j0 >> 2) - 2;        // global input row held in local row 0 (may be <0)

    __shared__ int xt[NR][XC + 3];          // staged input (clamped), local col c == global col c-2
    __shared__ int hb[NR][OW];              // horizontal-filtered rows
    __shared__ int cf[4][6];

    const int tid = threadIdx.x;
    if (tid < 24) cf[tid / 6][tid % 6] = CFILT[tid];

    const float* xim = x + (size_t)bc * (IH * IW);

    // ---- stage the (clamped) input window: NR rows x XC cols ----
    #pragma unroll
    for (int r = 0; r < NR; r++) {
        int g = rbase + r; if (g < 0) g = 0;           // row clamp (top only; bottom never binds)
        const float* row = xim + (size_t)g * IW;
        for (int c = tid; c < XC; c += 256) {
            int cg = c - 2; if (cg < 0) cg = 0;        // col clamp (left only)
            xt[r][c] = (int)__ldg(&row[cg]);
        }
    }
    __syncthreads();

    // ---- horizontal pass: hb[r][i] = sum_t cf[i&3][t] * x[r][ (i>>2)+t-2 ] ----
    for (int e = tid; e < NR * OW; e += 256) {
        int r = e / OW, i = e - r * OW;
        int xi = i >> 2, p = i & 3;
        int s = 0;
        #pragma unroll
        for (int t = 0; t < 6; t++) s += cf[p][t] * xt[r][xi + t];
        hb[r][i] = s;
    }
    __syncthreads();

    // ---- vertical pass + round + clamp + store ----
    float* oim = out + (size_t)bc * (OH * OW) + (size_t)j0 * OW;
    for (int e = tid; e < TJ * OW; e += 256) {
        int jl = e / OW, i = e - jl * OW;
        int q  = jl & 3;                    // j0 % 4 == 0
        int r0 = jl >> 2;                   // local row of tap t is r0 + t
        int s = 0;
        #pragma unroll
        for (int t = 0; t < 6; t++) s += cf[q][t] * hb[r0 + t][i];
        int v = (s + 8192) >> 14;           // floor((s+8192)/16384), exact incl. negatives
        v = min(max(v, 0), 255);
        oim[(size_t)jl * OW + i] = (float)v;
    }
}

extern "C" void kernel_launch(void* const* d_in, const int* in_sizes, int n_in,
                              void* d_out, int out_size) {
    const float* x = (const float*)d_in[0];
    float* out = (float*)d_out;
    dim3 grid(NBAND, NIMG);
    vtm_down_kernel<<<grid, 256>>>(x, out);
}

// round 2
// speedup vs baseline: 1.7097x; 1.7097x over previous
#include <cuda_runtime.h>
#include <stdint.h>

// VTM downsampler, register-tiled one-pass version.
//
// Reference index math: ref_pos = 4*i  =>  integer = i>>2, frac = 4*(i&3).
// Only FILTER rows {0,4,8,12} are used; nonzero taps are k=3..8 (offsets -2..+3).
// Row 0 is a delta (128 * center). All arithmetic exact in int32.
//
// Input : x  (8,3,1080,1920) f32 (integer-valued)   Output: (8,3,540,960) f32
// Each thread computes a 4(cols) x 4(rows) output tile from a 6x6 input window.
// Block = 240 threads = one 4-row output band across the full 960-wide output.

#define IH 1080
#define IW 1920
#define OH 540
#define OW 960
#define NIMG 24
#define XC 245          // staged cols: global -2..242 (L = gcol + 2)
#define XCP 248         // padded row stride

__global__ __launch_bounds__(240)
void vtm_down_kernel(const float* __restrict__ x, float* __restrict__ out) {
    const int bc   = blockIdx.y;     // image 0..23
    const int band = blockIdx.x;     // 0..134  (output rows 4*band .. 4*band+3)

    __shared__ int xt[6][XCP];       // input rows band-2 .. band+3 (row-clamped)

    const int tid = threadIdx.x;     // 0..239 : output-col tile index u
    const float* xim = x + (size_t)bc * (IH * IW);

    // ---- stage 6 x 245 clamped input window ----
    for (int e = tid; e < 6 * XC; e += 240) {
        int r = e / XC;
        int L = e - r * XC;
        int gr = band - 2 + r; if (gr < 0) gr = 0;   // top clamp only
        int gc = L - 2;        if (gc < 0) gc = 0;   // left clamp only
        xt[r][L] = (int)__ldg(&xim[(size_t)gr * IW + gc]);
    }
    __syncthreads();

    // ---- horizontal 6-tap, 4 phases, into registers ----
    int h0[6], h1[6], h2[6], h3[6];
    #pragma unroll
    for (int r = 0; r < 6; r++) {
        const int a = xt[r][tid];
        const int b = xt[r][tid + 1];
        const int c = xt[r][tid + 2];
        const int d = xt[r][tid + 3];
        const int e = xt[r][tid + 4];
        const int f = xt[r][tid + 5];
        h0[r] = c << 7;                                       // phase 0: delta
        h1[r] = 5*a - 18*b + 114*c + 36*d - 10*e + f;         // phase 1
        h2[r] = 4*(a + f) - 19*(b + e) + 79*(c + d);          // phase 2: symmetric
        h3[r] = a - 10*b + 36*c + 114*d - 18*e + 5*f;         // phase 3
    }

    // ---- vertical 6-tap, 4 phases, round, clamp, float4 store ----
    float* oim = out + (size_t)bc * (OH * OW) + (size_t)(band * 4) * OW + (tid * 4);

    // q = 0 : vertical delta (128 * row 2)
    {
        int s0 = h0[2] << 7, s1 = h1[2] << 7, s2 = h2[2] << 7, s3 = h3[2] << 7;
        float4 o;
        o.x = (float)min(max((s0 + 8192) >> 14, 0), 255);
        o.y = (float)min(max((s1 + 8192) >> 14, 0), 255);
        o.z = (float)min(max((s2 + 8192) >> 14, 0), 255);
        o.w = (float)min(max((s3 + 8192) >> 14, 0), 255);
        *(float4*)oim = o;
    }
    // q = 1
    {
        int s0 = 5*h0[0] - 18*h0[1] + 114*h0[2] + 36*h0[3] - 10*h0[4] + h0[5];
        int s1 = 5*h1[0] - 18*h1[1] + 114*h1[2] + 36*h1[3] - 10*h1[4] + h1[5];
        int s2 = 5*h2[0] - 18*h2[1] + 114*h2[2] + 36*h2[3] - 10*h2[4] + h2[5];
        int s3 = 5*h3[0] - 18*h3[1] + 114*h3[2] + 36*h3[3] - 10*h3[4] + h3[5];
        float4 o;
        o.x = (float)min(max((s0 + 8192) >> 14, 0), 255);
        o.y = (float)min(max((s1 + 8192) >> 14, 0), 255);
        o.z = (float)min(max((s2 + 8192) >> 14, 0), 255);
        o.w = (float)min(max((s3 + 8192) >> 14, 0), 255);
        *(float4*)(oim + OW) = o;
    }
    // q = 2 : symmetric
    {
        int s0 = 4*(h0[0] + h0[5]) - 19*(h0[1] + h0[4]) + 79*(h0[2] + h0[3]);
        int s1 = 4*(h1[0] + h1[5]) - 19*(h1[1] + h1[4]) + 79*(h1[2] + h1[3]);
        int s2 = 4*(h2[0] + h2[5]) - 19*(h2[1] + h2[4]) + 79*(h2[2] + h2[3]);
        int s3 = 4*(h3[0] + h3[5]) - 19*(h3[1] + h3[4]) + 79*(h3[2] + h3[3]);
        float4 o;
        o.x = (float)min(max((s0 + 8192) >> 14, 0), 255);
        o.y = (float)min(max((s1 + 8192) >> 14, 0), 255);
        o.z = (float)min(max((s2 + 8192) >> 14, 0), 255);
        o.w = (float)min(max((s3 + 8192) >> 14, 0), 255);
        *(float4*)(oim + 2 * OW) = o;
    }
    // q = 3
    {
        int s0 = h0[0] - 10*h0[1] + 36*h0[2] + 114*h0[3] - 18*h0[4] + 5*h0[5];
        int s1 = h1[0] - 10*h1[1] + 36*h1[2] + 114*h1[3] - 18*h1[4] + 5*h1[5];
        int s2 = h2[0] - 10*h2[1] + 36*h2[2] + 114*h2[3] - 18*h2[4] + 5*h2[5];
        int s3 = h3[0] - 10*h3[1] + 36*h3[2] + 114*h3[3] - 18*h3[4] + 5*h3[5];
        float4 o;
        o.x = (float)min(max((s0 + 8192) >> 14, 0), 255);
        o.y = (float)min(max((s1 + 8192) >> 14, 0), 255);
        o.z = (float)min(max((s2 + 8192) >> 14, 0), 255);
        o.w = (float)min(max((s3 + 8192) >> 14, 0), 255);
        *(float4*)(oim + 3 * OW) = o;
    }
}

extern "C" void kernel_launch(void* const* d_in, const int* in_sizes, int n_in,
                              void* d_out, int out_size) {
    const float* x = (const float*)d_in[0];
    float* out = (float*)d_out;
    dim3 grid(OH / 4, NIMG);       // 135 x 24
    vtm_down_kernel<<<grid, 240>>>(x, out);
}

// round 3
// speedup vs baseline: 2.6587x; 1.5551x over previous
#include <cuda_runtime.h>
#include <stdint.h>

// VTM downsampler — fp32 FFMA-immediate version, 16 output rows per block.
// Exact: all intermediates are integers < 2^24 (max |s| ~ 8.6M), fp32 arithmetic
// on them is exact; floor((s+8192)*2^-14) == (s+8192)>>14.
//
// Index math: integer = i>>2, frac = 4*(i&3) -> phases use FILTER rows {0,4,8,12},
// taps k=3..8 (offsets -2..+3). Phase 0 is a pure delta (128*center).

#define IH 1080
#define IW 1920
#define OH 540
#define OW 960
#define NIMG 24
#define XC 245           // staged cols: global -2..242 (local L = gcol+2)
#define XCP 248          // padded stride
#define NR 9             // staged rows: 4B-2 .. 4B+6 covers 16 output rows

// horizontal 6-tap filters applied to window a..f (= cols u-2..u+3)
#define HP1(a,b,c,d,e,f) fmaf(5.f,(a), fmaf(-18.f,(b), fmaf(114.f,(c), fmaf(36.f,(d), fmaf(-10.f,(e),(f))))))
#define HP2(a,b,c,d,e,f) fmaf(4.f,((a)+(f)), fmaf(-19.f,((b)+(e)), 79.f*((c)+(d))))
#define HP3(a,b,c,d,e,f) fmaf(5.f,(f), fmaf(-18.f,(e), fmaf(114.f,(d), fmaf(36.f,(c), fmaf(-10.f,(b),(a))))))

// vertical 6-tap on h[bl..bl+5], with +8192 rounding bias folded into the chain
#define VQ0(h) fmaf(128.f, h[bl+2], 8192.f)
#define VQ1(h) fmaf(5.f,h[bl+0], fmaf(-18.f,h[bl+1], fmaf(114.f,h[bl+2], fmaf(36.f,h[bl+3], fmaf(-10.f,h[bl+4], h[bl+5]+8192.f)))))
#define VQ2(h) fmaf(4.f,(h[bl+0]+h[bl+5]), fmaf(-19.f,(h[bl+1]+h[bl+4]), fmaf(79.f,(h[bl+2]+h[bl+3]), 8192.f)))
#define VQ3(h) fmaf(5.f,h[bl+5], fmaf(-18.f,h[bl+4], fmaf(114.f,h[bl+3], fmaf(36.f,h[bl+2], fmaf(-10.f,h[bl+1], h[bl+0]+8192.f)))))

__device__ __forceinline__ float fin(float s) {
    return fminf(fmaxf(floorf(s * 6.103515625e-5f), 0.f), 255.f);  // *2^-14, floor, clamp
}

__global__ __launch_bounds__(256)
void vtm_down_kernel(const float* __restrict__ x, float* __restrict__ out) {
    const int bc = blockIdx.y;            // image 0..23
    const int B  = blockIdx.x;            // 16-output-row super-band, 0..33

    __shared__ float xt[NR][XCP];

    const int tid = threadIdx.x;
    const float* xim = x + (size_t)bc * (IH * IW);
    const int r0 = 4 * B - 2;             // global input row of local row 0

    // ---- stage 9 x 245 clamped input window (pure float copy) ----
    for (int e = tid; e < NR * XC; e += 256) {
        int r = e / XC, L = e - r * XC;
        int gr = r0 + r; if (gr < 0) gr = 0;     // top clamp only
        int gc = L - 2;  if (gc < 0) gc = 0;     // left clamp only
        xt[r][L] = __ldg(&xim[(size_t)gr * IW + gc]);
    }
    __syncthreads();

    if (tid >= 240) return;               // 240 col-tiles of 4 outputs

    // ---- horizontal 6-tap, 4 phases, 9 rows -> registers ----
    float h0[NR], h1[NR], h2[NR], h3[NR];
    #pragma unroll
    for (int r = 0; r < NR; r++) {
        const float a = xt[r][tid];
        const float b = xt[r][tid + 1];
        const float c = xt[r][tid + 2];
        const float d = xt[r][tid + 3];
        const float e = xt[r][tid + 4];
        const float f = xt[r][tid + 5];
        h0[r] = 128.f * c;
        h1[r] = HP1(a, b, c, d, e, f);
        h2[r] = HP2(a, b, c, d, e, f);
        h3[r] = HP3(a, b, c, d, e, f);
    }

    // ---- vertical: 4 bands x 4 phases, round, clamp, float4 stores ----
    float* oim = out + (size_t)bc * (OH * OW) + (size_t)(16 * B) * OW + tid * 4;

    #pragma unroll
    for (int bl = 0; bl < 4; bl++) {
        const int jbase = 16 * B + 4 * bl;
        if (jbase < OH) {
            float* op = oim + (size_t)(4 * bl) * OW;
            float4 o;
            o.x = fin(VQ0(h0)); o.y = fin(VQ0(h1)); o.z = fin(VQ0(h2)); o.w = fin(VQ0(h3));
            *(float4*)op = o;
            o.x = fin(VQ1(h0)); o.y = fin(VQ1(h1)); o.z = fin(VQ1(h2)); o.w = fin(VQ1(h3));
            *(float4*)(op + OW) = o;
            o.x = fin(VQ2(h0)); o.y = fin(VQ2(h1)); o.z = fin(VQ2(h2)); o.w = fin(VQ2(h3));
            *(float4*)(op + 2 * OW) = o;
            o.x = fin(VQ3(h0)); o.y = fin(VQ3(h1)); o.z = fin(VQ3(h2)); o.w = fin(VQ3(h3));
            *(float4*)(op + 3 * OW) = o;
        }
    }
}

extern "C" void kernel_launch(void* const* d_in, const int* in_sizes, int n_in,
                              void* d_out, int out_size) {
    const float* x = (const float*)d_in[0];
    float* out = (float*)d_out;
    dim3 grid((OH + 15) / 16, NIMG);      // 34 x 24
    vtm_down_kernel<<<grid, 256>>>(x, out);
}

// round 4
// speedup vs baseline: 3.0930x; 1.1633x over previous
#include <cuda_runtime.h>
#include <stdint.h>

// VTM downsampler — fp32 FFMA-immediate, 8 output rows per block, 240 threads.
// Exact: all intermediates are integers < 2^24; fp32 on them is exact;
// floor((s+8192)*2^-14) == (s+8192)>>14.
//
// integer = i>>2, frac = 4*(i&3) -> FILTER rows {0,4,8,12}, taps k=3..8.
// Phase 0 is a pure delta (128*center); phase 2 is symmetric.

#define IH 1080
#define IW 1920
#define OH 540
#define OW 960
#define NIMG 24
#define XC 245           // staged cols: global -2..242 (local L = gcol+2)
#define XCP 248          // padded stride
#define NR 7             // staged rows: 2B-2 .. 2B+4 covers 8 output rows

#define HP1(a,b,c,d,e,f) fmaf(5.f,(a), fmaf(-18.f,(b), fmaf(114.f,(c), fmaf(36.f,(d), fmaf(-10.f,(e),(f))))))
#define HP2(a,b,c,d,e,f) fmaf(4.f,((a)+(f)), fmaf(-19.f,((b)+(e)), 79.f*((c)+(d))))
#define HP3(a,b,c,d,e,f) fmaf(5.f,(f), fmaf(-18.f,(e), fmaf(114.f,(d), fmaf(36.f,(c), fmaf(-10.f,(b),(a))))))

// vertical 6-tap on h[bl..bl+5], +8192 rounding bias folded in
#define VQ0(h) fmaf(128.f, h[bl+2], 8192.f)
#define VQ1(h) fmaf(5.f,h[bl+0], fmaf(-18.f,h[bl+1], fmaf(114.f,h[bl+2], fmaf(36.f,h[bl+3], fmaf(-10.f,h[bl+4], h[bl+5]+8192.f)))))
#define VQ2(h) fmaf(4.f,(h[bl+0]+h[bl+5]), fmaf(-19.f,(h[bl+1]+h[bl+4]), fmaf(79.f,(h[bl+2]+h[bl+3]), 8192.f)))
#define VQ3(h) fmaf(5.f,h[bl+5], fmaf(-18.f,h[bl+4], fmaf(114.f,h[bl+3], fmaf(36.f,h[bl+2], fmaf(-10.f,h[bl+1], h[bl+0]+8192.f)))))

__device__ __forceinline__ float fin(float s) {
    return fminf(fmaxf(floorf(s * 6.103515625e-5f), 0.f), 255.f);  // *2^-14, floor, clamp
}

__global__ __launch_bounds__(240, 5)
void vtm_down_kernel(const float* __restrict__ x, float* __restrict__ out) {
    const int bc = blockIdx.y;            // image 0..23
    const int B  = blockIdx.x;            // 8-output-row band, 0..67

    __shared__ float xt[NR][XCP];

    const int tid = threadIdx.x;          // 0..239 : output-col tile
    const float* xim = x + (size_t)bc * (IH * IW);
    const int r0 = 2 * B - 2;             // global input row of local row 0

    // ---- stage 7 x 245 clamped input window ----
    const int c0 = tid - 2 < 0 ? 0 : tid - 2;   // left clamp (tid<2 only)
    #pragma unroll
    for (int r = 0; r < NR; r++) {
        int gr = r0 + r; if (gr < 0) gr = 0;    // top clamp (B==0 only)
        const float* row = xim + (size_t)gr * IW;
        xt[r][tid] = __ldg(&row[c0]);
        if (tid < XC - 240) xt[r][240 + tid] = __ldg(&row[238 + tid]);
    }
    __syncthreads();

    // ---- horizontal 6-tap, 4 phases, 7 rows -> registers ----
    float h0[NR], h1[NR], h2[NR], h3[NR];
    #pragma unroll
    for (int r = 0; r < NR; r++) {
        const float a = xt[r][tid];
        const float b = xt[r][tid + 1];
        const float c = xt[r][tid + 2];
        const float d = xt[r][tid + 3];
        const float e = xt[r][tid + 4];
        const float f = xt[r][tid + 5];
        h0[r] = 128.f * c;
        h1[r] = HP1(a, b, c, d, e, f);
        h2[r] = HP2(a, b, c, d, e, f);
        h3[r] = HP3(a, b, c, d, e, f);
    }

    // ---- vertical: 2 bands x 4 phases, round, clamp, float4 stores ----
    float* oim = out + (size_t)bc * (OH * OW) + (size_t)(8 * B) * OW + tid * 4;

    #pragma unroll
    for (int bl = 0; bl < 2; bl++) {
        if (8 * B + 4 * bl < OH) {
            float* op = oim + (size_t)(4 * bl) * OW;
            float4 o;
            o.x = fin(VQ0(h0)); o.y = fin(VQ0(h1)); o.z = fin(VQ0(h2)); o.w = fin(VQ0(h3));
            *(float4*)op = o;
            o.x = fin(VQ1(h0)); o.y = fin(VQ1(h1)); o.z = fin(VQ1(h2)); o.w = fin(VQ1(h3));
            *(float4*)(op + OW) = o;
            o.x = fin(VQ2(h0)); o.y = fin(VQ2(h1)); o.z = fin(VQ2(h2)); o.w = fin(VQ2(h3));
            *(float4*)(op + 2 * OW) = o;
            o.x = fin(VQ3(h0)); o.y = fin(VQ3(h1)); o.z = fin(VQ3(h2)); o.w = fin(VQ3(h3));
            *(float4*)(op + 3 * OW) = o;
        }
    }
}

extern "C" void kernel_launch(void* const* d_in, const int* in_sizes, int n_in,
                              void* d_out, int out_size) {
    const float* x = (const float*)d_in[0];
    float* out = (float*)d_out;
    dim3 grid((OH + 7) / 8, NIMG);        // 68 x 24 = 1632 blocks
    vtm_down_kernel<<<grid, 240>>>(x, out);
}